// round 15
// baseline (speedup 1.0000x reference)
#include <cuda_runtime.h>
#include <cstdint>

// Scratch: split-K partials [8][512*256] (4 MB) and x3 [512 x 64].
static __device__ float g_part[8][512 * 256];
static __device__ float g_x3[512 * 64];

__device__ __forceinline__ void cp_async16(void* smem_dst, const void* gmem_src) {
    uint32_t s = (uint32_t)__cvta_generic_to_shared(smem_dst);
    asm volatile("cp.async.cg.shared.global [%0], [%1], 16;"
                 :: "r"(s), "l"(gmem_src));
}

// ---------------------------------------------------------------------------
// Kernel A1: split-K partial GEMM with cp.async double buffering.
//   part[z] = x[32r x 64k] @ w2^T[64k x 64h], K processed as 2 chunks of 32.
// grid (16, 4, 8) = 512 blocks, 128 threads, ~27.6KB smem -> single wave.
// Chunk1's load latency is hidden under chunk0's compute.
// ---------------------------------------------------------------------------
__global__ void __launch_bounds__(128) gemm1_part_kernel(
    const float* __restrict__ x,    // [512, 512]
    const float* __restrict__ w2)   // [256, 512]
{
    __shared__ float xs[2][32][36];
    __shared__ float ws[2][64][36];

    const int t  = threadIdx.x;
    const int r0 = blockIdx.x * 32;
    const int h0 = blockIdx.y * 64;
    const int k0 = blockIdx.z * 64;

    // prefetch both 32-k chunks (6 cp.async of 16B per thread per chunk)
    #pragma unroll
    for (int s = 0; s < 2; ++s) {
        const int kc = k0 + s * 32;
        #pragma unroll
        for (int i = 0; i < 2; ++i) {
            const int idx = t + i * 128;
            const int r   = idx >> 3;
            const int kq  = (idx & 7) * 4;
            cp_async16(&xs[s][r][kq], x + (size_t)(r0 + r) * 512 + kc + kq);
        }
        #pragma unroll
        for (int i = 0; i < 4; ++i) {
            const int idx = t + i * 128;
            const int r   = idx >> 3;
            const int kq  = (idx & 7) * 4;
            cp_async16(&ws[s][r][kq], w2 + (size_t)(h0 + r) * 512 + kc + kq);
        }
        asm volatile("cp.async.commit_group;" ::: "memory");
    }

    float acc[4][4];
    #pragma unroll
    for (int i = 0; i < 4; ++i)
        #pragma unroll
        for (int j = 0; j < 4; ++j) acc[i][j] = 0.f;

    const int tx = t & 15;   // cols tx, tx+16, tx+32, tx+48
    const int ty = t >> 4;   // rows ty, ty+8, ty+16, ty+24

    // wait for chunk 0 only (chunk 1 still in flight)
    asm volatile("cp.async.wait_group 1;" ::: "memory");
    __syncthreads();

    #pragma unroll
    for (int kq = 0; kq < 32; kq += 4) {
        float4 a[4], bv[4];
        #pragma unroll
        for (int i = 0; i < 4; ++i)
            a[i] = *reinterpret_cast<const float4*>(&xs[0][ty + 8 * i][kq]);
        #pragma unroll
        for (int j = 0; j < 4; ++j)
            bv[j] = *reinterpret_cast<const float4*>(&ws[0][tx + 16 * j][kq]);
        #pragma unroll
        for (int i = 0; i < 4; ++i)
            #pragma unroll
            for (int j = 0; j < 4; ++j) {
                acc[i][j] = fmaf(a[i].x, bv[j].x, acc[i][j]);
                acc[i][j] = fmaf(a[i].y, bv[j].y, acc[i][j]);
                acc[i][j] = fmaf(a[i].z, bv[j].z, acc[i][j]);
                acc[i][j] = fmaf(a[i].w, bv[j].w, acc[i][j]);
            }
    }

    // chunk 1
    asm volatile("cp.async.wait_group 0;" ::: "memory");
    __syncthreads();

    #pragma unroll
    for (int kq = 0; kq < 32; kq += 4) {
        float4 a[4], bv[4];
        #pragma unroll
        for (int i = 0; i < 4; ++i)
            a[i] = *reinterpret_cast<const float4*>(&xs[1][ty + 8 * i][kq]);
        #pragma unroll
        for (int j = 0; j < 4; ++j)
            bv[j] = *reinterpret_cast<const float4*>(&ws[1][tx + 16 * j][kq]);
        #pragma unroll
        for (int i = 0; i < 4; ++i)
            #pragma unroll
            for (int j = 0; j < 4; ++j) {
                acc[i][j] = fmaf(a[i].x, bv[j].x, acc[i][j]);
                acc[i][j] = fmaf(a[i].y, bv[j].y, acc[i][j]);
                acc[i][j] = fmaf(a[i].z, bv[j].z, acc[i][j]);
                acc[i][j] = fmaf(a[i].w, bv[j].w, acc[i][j]);
            }
    }

    float* dst = g_part[blockIdx.z];
    #pragma unroll
    for (int i = 0; i < 4; ++i)
        #pragma unroll
        for (int j = 0; j < 4; ++j)
            dst[(size_t)(r0 + ty + 8 * i) * 256 + h0 + tx + 16 * j] = acc[i][j];
}

// ---------------------------------------------------------------------------
// Kernel A2 v3: parallel head.  256 blocks x 256 threads, 2 rows per block.
// ---------------------------------------------------------------------------
__global__ void __launch_bounds__(256) head_kernel(
    const float* __restrict__ b2,   // [256]
    const float* __restrict__ w3,   // [55, 256]
    const float* __restrict__ b3)   // [55]
{
    __shared__ float hs[2][260];
    __shared__ float zp[110][2];
    __shared__ float zs[2][60];

    const int t  = threadIdx.x;
    const int r0 = blockIdx.x * 2;

    if (t < 128) {
        const int i  = t >> 6;
        const int cg = t & 63;
        float4 acc = *reinterpret_cast<const float4*>(b2 + cg * 4);
        const size_t off = (size_t)(r0 + i) * 256 + cg * 4;
        #pragma unroll
        for (int z = 0; z < 8; ++z) {
            const float4 v = *reinterpret_cast<const float4*>(&g_part[z][off]);
            acc.x += v.x; acc.y += v.y; acc.z += v.z; acc.w += v.w;
        }
        acc.x = (acc.x >= 0.f) ? acc.x : 0.01f * acc.x;
        acc.y = (acc.y >= 0.f) ? acc.y : 0.01f * acc.y;
        acc.z = (acc.z >= 0.f) ? acc.z : 0.01f * acc.z;
        acc.w = (acc.w >= 0.f) ? acc.w : 0.01f * acc.w;
        *reinterpret_cast<float4*>(&hs[i][cg * 4]) = acc;
    }
    __syncthreads();

    if (t < 220) {
        const int o    = t >> 1;
        const int half = t & 1;
        const int r    = o & 1;
        const int c    = o >> 1;
        const float4* hv = reinterpret_cast<const float4*>(&hs[r][half * 128]);
        const float4* wv = reinterpret_cast<const float4*>(
            w3 + (size_t)c * 256 + half * 128);
        float acc = 0.f;
        #pragma unroll 8
        for (int k = 0; k < 32; ++k) {
            const float4 a = hv[k];
            const float4 w = __ldg(&wv[k]);
            acc = fmaf(a.x, w.x, acc); acc = fmaf(a.y, w.y, acc);
            acc = fmaf(a.z, w.z, acc); acc = fmaf(a.w, w.w, acc);
        }
        zp[o][half] = acc;
    }
    __syncthreads();

    if (t < 110) {
        const int r = t & 1;
        const int c = t >> 1;
        zs[r][c] = zp[t][0] + zp[t][1] + b3[c];
    }
    __syncthreads();

    if (t < 12) {
        const int r     = t / 6;
        const int g     = t - 6 * r;
        const int start = (g == 0) ? 0 : 5 + 10 * (g - 1);
        const int len   = (g == 0) ? 5 : 10;
        float m = -3.0e38f;
        for (int c = 0; c < len; ++c) m = fmaxf(m, zs[r][start + c]);
        float s = 0.f;
        for (int c = 0; c < len; ++c) s += __expf(zs[r][start + c] - m);
        const float inv = 1.0f / s;
        float* dst = &g_x3[(size_t)(r0 + r) * 64];
        for (int c = 0; c < len; ++c)
            dst[start + c] = __expf(zs[r][start + c] - m) * inv;
    }
}

// ---------------------------------------------------------------------------
// Kernel B: expansion.  out[b, i] constant over runs of 10 (r = i/10).
// grid (8, 512), 640 threads; loop-invariant per-thread run phase;
// streaming (evict-first) float4 stores.  [R8/R13 form — best measured]
// ---------------------------------------------------------------------------
__global__ void __launch_bounds__(640) expand_kernel(float* __restrict__ out)
{
    __shared__ float p[64];
    __shared__ float sv[1288];

    const unsigned t   = threadIdx.x;
    const unsigned bx  = blockIdx.x;
    const unsigned b   = blockIdx.y;
    const unsigned pad = b & 3u;
    const unsigned rbase = bx * 1280u;   // multiple of 10

    if (t < 64u) p[t] = g_x3[(size_t)b * 64u + t];
    __syncthreads();

    #pragma unroll
    for (unsigned kk = 0; kk < 3u; ++kk) {
        const unsigned ri = t + kk * 640u;
        if (ri < 1282u) {
            const unsigned r = rbase + ri;
            float v = 0.f;
            if (r < 10000u) {
                if (r == 0u) {
                    v = p[0];
                } else if (r < 10u) {
                    v = p[1] * p[5 + r];
                } else if (r < 100u) {
                    const unsigned q1 = r / 10u;
                    v = p[2] * p[5 + q1] * p[15 + (r - 10u * q1)];
                } else if (r < 1000u) {
                    const unsigned q1 = r / 10u, q2 = r / 100u;
                    v = p[3] * p[5 + q2] * p[15 + (q1 - 10u * q2)]
                             * p[25 + (r - 10u * q1)];
                } else {
                    const unsigned q1 = r / 10u, q2 = r / 100u, q3 = r / 1000u;
                    v = p[4] * p[5 + q3] * p[15 + (q2 - 10u * q3)]
                             * p[25 + (q1 - 10u * q2)] * p[35 + (r - 10u * q1)];
                }
            }
            sv[ri] = v;
        }
    }
    __syncthreads();

    float* o = out + (size_t)b * 99999u;
    float4* ov = reinterpret_cast<float4*>(o + pad);   // 16B-aligned

    const unsigned ph  = pad + 4u * t;       // < 2563
    const unsigned rt  = ph / 10u;
    const unsigned rem = ph - 10u * rt;
    const bool c1 = (rem + 1u < 10u);
    const bool c2 = (rem + 2u < 10u);
    const bool c3 = (rem + 3u < 10u);

    if (bx < 7u) {
        unsigned vi = bx * 3200u + t;
        unsigned ri = rt;
        #pragma unroll
        for (int k = 0; k < 5; ++k) {
            const float f0 = sv[ri];
            const float f1 = sv[ri + 1u];
            float4 w;
            w.x = f0;
            w.y = c1 ? f0 : f1;
            w.z = c2 ? f0 : f1;
            w.w = c3 ? f0 : f1;
            __stcs(&ov[vi], w);
            vi += 640u;
            ri += 256u;
        }
        if (bx == 0u) {
            if (t == 0u) o[0] = p[1] * p[5];
            else if (t < pad) o[t] = p[0];   // pad <= 3
        }
    } else {
        unsigned vi = 22400u + t;
        unsigned ri = rt;
        #pragma unroll
        for (int k = 0; k < 5; ++k) {
            if (vi < 24999u) {
                const float f0 = sv[ri];
                const float f1 = sv[ri + 1u];
                float4 w;
                w.x = f0;
                w.y = c1 ? f0 : f1;
                w.z = c2 ? f0 : f1;
                w.w = c3 ? f0 : f1;
                __stcs(&ov[vi], w);
            }
            vi += 640u;
            ri += 256u;
        }
        if (t < 3u - pad) {
            o[pad + 99996u + t] = sv[1039];
        }
    }
}

// ---------------------------------------------------------------------------
extern "C" void kernel_launch(void* const* d_in, const int* in_sizes, int n_in,
                              void* d_out, int out_size)
{
    (void)in_sizes; (void)n_in; (void)out_size;
    const float* x  = (const float*)d_in[0];   // [512, 512]
    const float* w2 = (const float*)d_in[1];   // [256, 512]
    const float* b2 = (const float*)d_in[2];   // [256]
    const float* w3 = (const float*)d_in[3];   // [55, 256]
    const float* b3 = (const float*)d_in[4];   // [55]
    float* out = (float*)d_out;                // [512, 99999]

    gemm1_part_kernel<<<dim3(16, 4, 8), 128>>>(x, w2);
    head_kernel<<<256, 256>>>(b2, w3, b3);
    expand_kernel<<<dim3(8, 512), 640>>>(out);
}

// round 16
// speedup vs baseline: 1.0303x; 1.0303x over previous
#include <cuda_runtime.h>

// Scratch: split-K partials [16][512*256] (8 MB) and x3 [512 x 64].
static __device__ float g_part[16][512 * 256];
static __device__ float g_x3[512 * 64];

#if defined(__CUDA_ARCH__) && (__CUDA_ARCH__ >= 900)
#define GRID_DEP_SYNC()  cudaGridDependencySynchronize()
#define GRID_DEP_TRIG()  cudaTriggerProgrammaticLaunchCompletion()
#else
#define GRID_DEP_SYNC()
#define GRID_DEP_TRIG()
#endif

// ---------------------------------------------------------------------------
// Kernel A1: split-K partial GEMM.  part[z] = x[32r x 32k] @ w2^T[32k x 64h]
// grid (16, 4, 16) = 1024 blocks, 128 threads, all resident.  [R8 form]
// ---------------------------------------------------------------------------
__global__ void __launch_bounds__(128) gemm1_part_kernel(
    const float* __restrict__ x,    // [512, 512]
    const float* __restrict__ w2)   // [256, 512]
{
    __shared__ float xs[32][36];
    __shared__ float ws[64][36];

    const int t  = threadIdx.x;
    const int r0 = blockIdx.x * 32;
    const int h0 = blockIdx.y * 64;
    const int k0 = blockIdx.z * 32;

    #pragma unroll
    for (int i = 0; i < 2; ++i) {
        const int idx = t + i * 128;
        const int r   = idx >> 3;
        const int kq  = (idx & 7) * 4;
        float4 v = *reinterpret_cast<const float4*>(
            x + (size_t)(r0 + r) * 512 + k0 + kq);
        *reinterpret_cast<float4*>(&xs[r][kq]) = v;
    }
    #pragma unroll
    for (int i = 0; i < 4; ++i) {
        const int idx = t + i * 128;
        const int r   = idx >> 3;
        const int kq  = (idx & 7) * 4;
        float4 v = *reinterpret_cast<const float4*>(
            w2 + (size_t)(h0 + r) * 512 + k0 + kq);
        *reinterpret_cast<float4*>(&ws[r][kq]) = v;
    }

    float acc[4][4];
    #pragma unroll
    for (int i = 0; i < 4; ++i)
        #pragma unroll
        for (int j = 0; j < 4; ++j) acc[i][j] = 0.f;

    const int tx = t & 15;
    const int ty = t >> 4;

    __syncthreads();

    #pragma unroll
    for (int kq = 0; kq < 32; kq += 4) {
        float4 a[4], bv[4];
        #pragma unroll
        for (int i = 0; i < 4; ++i)
            a[i] = *reinterpret_cast<const float4*>(&xs[ty + 8 * i][kq]);
        #pragma unroll
        for (int j = 0; j < 4; ++j)
            bv[j] = *reinterpret_cast<const float4*>(&ws[tx + 16 * j][kq]);
        #pragma unroll
        for (int i = 0; i < 4; ++i)
            #pragma unroll
            for (int j = 0; j < 4; ++j) {
                acc[i][j] = fmaf(a[i].x, bv[j].x, acc[i][j]);
                acc[i][j] = fmaf(a[i].y, bv[j].y, acc[i][j]);
                acc[i][j] = fmaf(a[i].z, bv[j].z, acc[i][j]);
                acc[i][j] = fmaf(a[i].w, bv[j].w, acc[i][j]);
            }
    }

    float* dst = g_part[blockIdx.z];
    #pragma unroll
    for (int i = 0; i < 4; ++i)
        #pragma unroll
        for (int j = 0; j < 4; ++j)
            dst[(size_t)(r0 + ty + 8 * i) * 256 + h0 + tx + 16 * j] = acc[i][j];

    GRID_DEP_TRIG();   // partials written -> dependent may consume
}

// ---------------------------------------------------------------------------
// Kernel A2 v3: parallel head.  256 blocks x 256 threads, 2 rows per block.
// PDL: sync before reading g_part; trigger after g_x3 stores.
// ---------------------------------------------------------------------------
__global__ void __launch_bounds__(256) head_kernel(
    const float* __restrict__ b2,   // [256]
    const float* __restrict__ w3,   // [55, 256]
    const float* __restrict__ b3)   // [55]
{
    __shared__ float hs[2][260];
    __shared__ float zp[110][2];
    __shared__ float zs[2][60];

    const int t  = threadIdx.x;
    const int r0 = blockIdx.x * 2;

    GRID_DEP_SYNC();   // wait for gemm1's partials

    if (t < 128) {
        const int i  = t >> 6;
        const int cg = t & 63;
        float4 acc = *reinterpret_cast<const float4*>(b2 + cg * 4);
        const size_t off = (size_t)(r0 + i) * 256 + cg * 4;
        #pragma unroll
        for (int z = 0; z < 16; ++z) {
            const float4 v = *reinterpret_cast<const float4*>(&g_part[z][off]);
            acc.x += v.x; acc.y += v.y; acc.z += v.z; acc.w += v.w;
        }
        acc.x = (acc.x >= 0.f) ? acc.x : 0.01f * acc.x;
        acc.y = (acc.y >= 0.f) ? acc.y : 0.01f * acc.y;
        acc.z = (acc.z >= 0.f) ? acc.z : 0.01f * acc.z;
        acc.w = (acc.w >= 0.f) ? acc.w : 0.01f * acc.w;
        *reinterpret_cast<float4*>(&hs[i][cg * 4]) = acc;
    }
    __syncthreads();

    if (t < 220) {
        const int o    = t >> 1;
        const int half = t & 1;
        const int r    = o & 1;
        const int c    = o >> 1;
        const float4* hv = reinterpret_cast<const float4*>(&hs[r][half * 128]);
        const float4* wv = reinterpret_cast<const float4*>(
            w3 + (size_t)c * 256 + half * 128);
        float acc = 0.f;
        #pragma unroll 8
        for (int k = 0; k < 32; ++k) {
            const float4 a = hv[k];
            const float4 w = __ldg(&wv[k]);
            acc = fmaf(a.x, w.x, acc); acc = fmaf(a.y, w.y, acc);
            acc = fmaf(a.z, w.z, acc); acc = fmaf(a.w, w.w, acc);
        }
        zp[o][half] = acc;
    }
    __syncthreads();

    if (t < 110) {
        const int r = t & 1;
        const int c = t >> 1;
        zs[r][c] = zp[t][0] + zp[t][1] + b3[c];
    }
    __syncthreads();

    if (t < 12) {
        const int r     = t / 6;
        const int g     = t - 6 * r;
        const int start = (g == 0) ? 0 : 5 + 10 * (g - 1);
        const int len   = (g == 0) ? 5 : 10;
        float m = -3.0e38f;
        for (int c = 0; c < len; ++c) m = fmaxf(m, zs[r][start + c]);
        float s = 0.f;
        for (int c = 0; c < len; ++c) s += __expf(zs[r][start + c] - m);
        const float inv = 1.0f / s;
        float* dst = &g_x3[(size_t)(r0 + r) * 64];
        for (int c = 0; c < len; ++c)
            dst[start + c] = __expf(zs[r][start + c] - m) * inv;
    }

    GRID_DEP_TRIG();   // x3 written -> expand may consume
}

// ---------------------------------------------------------------------------
// Kernel B: expansion.  out[b, i] constant over runs of 10 (r = i/10).
// grid (8, 512), 640 threads; loop-invariant per-thread run phase;
// streaming (evict-first) float4 stores.  [R8/R13 form]
// PDL: all row-independent setup hoisted above the dependency sync.
// ---------------------------------------------------------------------------
__global__ void __launch_bounds__(640) expand_kernel(float* __restrict__ out)
{
    __shared__ float p[64];
    __shared__ float sv[1288];

    const unsigned t   = threadIdx.x;
    const unsigned bx  = blockIdx.x;
    const unsigned b   = blockIdx.y;
    const unsigned pad = b & 3u;
    const unsigned rbase = bx * 1280u;   // multiple of 10

    // --- row-independent setup (runs before head finishes) ---
    const unsigned ph  = pad + 4u * t;       // < 2563
    const unsigned rt  = ph / 10u;
    const unsigned rem = ph - 10u * rt;
    const bool c1 = (rem + 1u < 10u);
    const bool c2 = (rem + 2u < 10u);
    const bool c3 = (rem + 3u < 10u);
    float* o = out + (size_t)b * 99999u;
    float4* ov = reinterpret_cast<float4*>(o + pad);   // 16B-aligned

    GRID_DEP_SYNC();   // wait for head's g_x3

    if (t < 64u) p[t] = g_x3[(size_t)b * 64u + t];
    __syncthreads();

    #pragma unroll
    for (unsigned kk = 0; kk < 3u; ++kk) {
        const unsigned ri = t + kk * 640u;
        if (ri < 1282u) {
            const unsigned r = rbase + ri;
            float v = 0.f;
            if (r < 10000u) {
                if (r == 0u) {
                    v = p[0];
                } else if (r < 10u) {
                    v = p[1] * p[5 + r];
                } else if (r < 100u) {
                    const unsigned q1 = r / 10u;
                    v = p[2] * p[5 + q1] * p[15 + (r - 10u * q1)];
                } else if (r < 1000u) {
                    const unsigned q1 = r / 10u, q2 = r / 100u;
                    v = p[3] * p[5 + q2] * p[15 + (q1 - 10u * q2)]
                             * p[25 + (r - 10u * q1)];
                } else {
                    const unsigned q1 = r / 10u, q2 = r / 100u, q3 = r / 1000u;
                    v = p[4] * p[5 + q3] * p[15 + (q2 - 10u * q3)]
                             * p[25 + (q1 - 10u * q2)] * p[35 + (r - 10u * q1)];
                }
            }
            sv[ri] = v;
        }
    }
    __syncthreads();

    if (bx < 7u) {
        unsigned vi = bx * 3200u + t;
        unsigned ri = rt;
        #pragma unroll
        for (int k = 0; k < 5; ++k) {
            const float f0 = sv[ri];
            const float f1 = sv[ri + 1u];
            float4 w;
            w.x = f0;
            w.y = c1 ? f0 : f1;
            w.z = c2 ? f0 : f1;
            w.w = c3 ? f0 : f1;
            __stcs(&ov[vi], w);
            vi += 640u;
            ri += 256u;
        }
        if (bx == 0u) {
            if (t == 0u) o[0] = p[1] * p[5];
            else if (t < pad) o[t] = p[0];   // pad <= 3
        }
    } else {
        unsigned vi = 22400u + t;
        unsigned ri = rt;
        #pragma unroll
        for (int k = 0; k < 5; ++k) {
            if (vi < 24999u) {
                const float f0 = sv[ri];
                const float f1 = sv[ri + 1u];
                float4 w;
                w.x = f0;
                w.y = c1 ? f0 : f1;
                w.z = c2 ? f0 : f1;
                w.w = c3 ? f0 : f1;
                __stcs(&ov[vi], w);
            }
            vi += 640u;
            ri += 256u;
        }
        if (t < 3u - pad) {
            o[pad + 99996u + t] = sv[1039];
        }
    }
}

// ---------------------------------------------------------------------------
extern "C" void kernel_launch(void* const* d_in, const int* in_sizes, int n_in,
                              void* d_out, int out_size)
{
    (void)in_sizes; (void)n_in; (void)out_size;
    const float* x  = (const float*)d_in[0];   // [512, 512]
    const float* w2 = (const float*)d_in[1];   // [256, 512]
    const float* b2 = (const float*)d_in[2];   // [256]
    const float* w3 = (const float*)d_in[3];   // [55, 256]
    const float* b3 = (const float*)d_in[4];   // [55]
    float* out = (float*)d_out;                // [512, 99999]

    // 1) gemm1 — plain launch
    gemm1_part_kernel<<<dim3(16, 4, 16), 128>>>(x, w2);

    // 2) head — PDL after gemm1
    {
        cudaLaunchConfig_t cfg = {};
        cfg.gridDim  = dim3(256, 1, 1);
        cfg.blockDim = dim3(256, 1, 1);
        cudaLaunchAttribute attr[1];
        attr[0].id = cudaLaunchAttributeProgrammaticStreamSerialization;
        attr[0].val.programmaticStreamSerializationAllowed = 1;
        cfg.attrs = attr;
        cfg.numAttrs = 1;
        cudaLaunchKernelEx(&cfg, head_kernel, b2, w3, b3);
    }

    // 3) expand — PDL after head
    {
        cudaLaunchConfig_t cfg = {};
        cfg.gridDim  = dim3(8, 512, 1);
        cfg.blockDim = dim3(640, 1, 1);
        cudaLaunchAttribute attr[1];
        attr[0].id = cudaLaunchAttributeProgrammaticStreamSerialization;
        attr[0].val.programmaticStreamSerializationAllowed = 1;
        cfg.attrs = attr;
        cfg.numAttrs = 1;
        cudaLaunchKernelEx(&cfg, expand_kernel, out);
    }
}